// round 10
// baseline (speedup 1.0000x reference)
#include <cuda_runtime.h>
#include <cstdint>
#include <math.h>

#define S_LEN 2048
#define D_MODEL 2048
#define NHEAD 32
#define HDIM 64
#define FF_DIM 8192
#define QKV_N (3 * D_MODEL)

// ---------------- scratch (static device globals; no allocation) ----------------
__device__ float g_h  [S_LEN * D_MODEL];
__device__ float g_qkv[S_LEN * QKV_N];
__device__ float g_vT [D_MODEL * S_LEN];   // V transposed: [dim_global][seq]
__device__ float g_ctx[S_LEN * D_MODEL];
__device__ float g_res[S_LEN * D_MODEL];
__device__ float g_h2 [S_LEN * D_MODEL];
__device__ float g_mlp[S_LEN * FF_DIM];
// transposed tf32 weights (K-major)
__device__ float g_wqkvT[QKV_N * D_MODEL];
__device__ float g_woT  [D_MODEL * D_MODEL];
__device__ float g_w1T  [FF_DIM * D_MODEL];
__device__ float g_w2T  [D_MODEL * FF_DIM];

// ================= helpers =================
__device__ __forceinline__ uint32_t smem_u32(const void* p) {
    uint32_t a;
    asm("{ .reg .u64 t; cvta.to.shared.u64 t, %1; cvt.u32.u64 %0, t; }" : "=r"(a) : "l"(p));
    return a;
}
__device__ __forceinline__ uint32_t f2tf32(float f) {
    uint32_t u;
    asm("cvt.rna.tf32.f32 %0, %1;" : "=r"(u) : "f"(f));
    return u;
}
__device__ __forceinline__ float rnd_tf32(float f) { return __uint_as_float(f2tf32(f)); }

__device__ __forceinline__ void mma_tf32(float* d, const uint32_t* a, const uint32_t* b) {
    asm volatile(
        "mma.sync.aligned.m16n8k8.row.col.f32.tf32.tf32.f32 "
        "{%0,%1,%2,%3}, {%4,%5,%6,%7}, {%8,%9}, {%0,%1,%2,%3};"
        : "+f"(d[0]), "+f"(d[1]), "+f"(d[2]), "+f"(d[3])
        : "r"(a[0]), "r"(a[1]), "r"(a[2]), "r"(a[3]), "r"(b[0]), "r"(b[1]));
}
__device__ __forceinline__ void ldsm4(uint32_t* r, uint32_t addr) {
    asm volatile("ldmatrix.sync.aligned.m8n8.x4.shared.b16 {%0,%1,%2,%3}, [%4];"
                 : "=r"(r[0]), "=r"(r[1]), "=r"(r[2]), "=r"(r[3]) : "r"(addr));
}
__device__ __forceinline__ void cpa16(uint32_t dst, const float* src) {
    asm volatile("cp.async.cg.shared.global [%0], [%1], 16;" :: "r"(dst), "l"(src));
}
#define CP_COMMIT() asm volatile("cp.async.commit_group;" ::: "memory")
#define CP_WAIT(n)  asm volatile("cp.async.wait_group %0;" :: "n"(n) : "memory")

// ================= weight transpose + tf32 convert =================
__global__ __launch_bounds__(256)
void transpose_tf32(const float* __restrict__ W, float* __restrict__ WT, int K, int N)
{
    __shared__ float t[32][33];
    int n0 = blockIdx.x * 32, k0 = blockIdx.y * 32;
    int tx = threadIdx.x & 31, ty = threadIdx.x >> 5;
#pragma unroll
    for (int r = 0; r < 32; r += 8)
        t[ty + r][tx] = W[(size_t)(k0 + ty + r) * N + n0 + tx];
    __syncthreads();
#pragma unroll
    for (int r = 0; r < 32; r += 8)
        WT[(size_t)(n0 + ty + r) * K + k0 + tx] = rnd_tf32(t[tx][ty + r]);
}

// ================= tf32 tensor-core GEMM (pure cp.async + ldmatrix) ========
// C[M,N] = A[M,K] @ BT[N,K]^T.  128x128 block tile, K-chunk 32, double-buffered.
// 8 warps = 4(m) x 2(n); warp tile 32x64; mma m16n8k8.
// EPI 0: +bias   EPI 1: +bias+resid   EPI 2: tf32(gelu(+bias))
// EPI 3: QKV — tf32-rounded; V columns (c>=4096) written transposed to vT(resid ptr)
#define TS_STRIDE 36
#define A_TILE_F (128 * TS_STRIDE)
#define STAGE_F  (2 * A_TILE_F)
#define GEMM_SMEM (2 * STAGE_F * 4)     // 73,728 B

template<int EPI>
__global__ __launch_bounds__(256, 2)
void mma_gemm(const float* __restrict__ A, const float* __restrict__ BT,
              const float* __restrict__ bias, const float* __restrict__ resid,
              float* __restrict__ C, int M, int N, int K)
{
    extern __shared__ float sm[];
    uint32_t sbase = smem_u32(sm);

    int tid = threadIdx.x;
    int lane = tid & 31, wid = tid >> 5;
    int wm = wid & 3, wn = wid >> 2;
    int m0 = blockIdx.y * 128, n0 = blockIdx.x * 128;

    auto load_tile = [&](int st, int k0) {
        uint32_t base = sbase + (uint32_t)st * STAGE_F * 4;
        int r = tid >> 3, kq = tid & 7;
#pragma unroll
        for (int q = 0; q < 4; q++) {
            int row = r + q * 32;
            cpa16(base + (uint32_t)(row * TS_STRIDE + kq * 4) * 4,
                  A + (size_t)(m0 + row) * K + k0 + kq * 4);
        }
#pragma unroll
        for (int q = 0; q < 4; q++) {
            int row = r + q * 32;
            cpa16(base + (uint32_t)(A_TILE_F + row * TS_STRIDE + kq * 4) * 4,
                  BT + (size_t)(n0 + row) * K + k0 + kq * 4);
        }
        CP_COMMIT();
    };

    float acc[2][8][4];
#pragma unroll
    for (int i = 0; i < 2; i++)
#pragma unroll
        for (int j = 0; j < 8; j++)
#pragma unroll
            for (int c = 0; c < 4; c++) acc[i][j][c] = 0.f;

    int midx = lane >> 3, mrow = lane & 7;
    int a_row_off = (midx & 1) * 8 + mrow;
    int a_col_off = (midx >> 1) * 4;
    int b_row_base = wn * 64 + (midx >> 1) * 8 + mrow;
    int b_col_off = (midx & 1) * 4;

    const int T = K / 32;

    load_tile(0, 0);

    for (int i = 0; i < T; i++) {
        int st = i & 1;
        if (i + 1 < T) {
            load_tile(st ^ 1, (i + 1) * 32);
            CP_WAIT(1);
        } else {
            CP_WAIT(0);
        }
        __syncthreads();

        uint32_t abase = sbase + (uint32_t)st * STAGE_F * 4;
        uint32_t bbase = abase + A_TILE_F * 4;
#pragma unroll
        for (int ks = 0; ks < 4; ks++) {
            int kb = ks * 8;
            uint32_t af[2][4];
#pragma unroll
            for (int mi = 0; mi < 2; mi++) {
                int r = wm * 32 + mi * 16 + a_row_off;
                ldsm4(af[mi], abase + (uint32_t)(r * TS_STRIDE + kb + a_col_off) * 4);
            }
            uint32_t bf[8][2];
#pragma unroll
            for (int jj = 0; jj < 4; jj++) {
                uint32_t t4[4];
                int r = b_row_base + jj * 16;
                ldsm4(t4, bbase + (uint32_t)(r * TS_STRIDE + kb + b_col_off) * 4);
                bf[jj * 2 + 0][0] = t4[0]; bf[jj * 2 + 0][1] = t4[1];
                bf[jj * 2 + 1][0] = t4[2]; bf[jj * 2 + 1][1] = t4[3];
            }
#pragma unroll
            for (int mi = 0; mi < 2; mi++)
#pragma unroll
                for (int nj = 0; nj < 8; nj++)
                    mma_tf32(acc[mi][nj], af[mi], bf[nj]);
        }
        __syncthreads();
    }

    // ---- epilogue ----
    int g = lane >> 2, t = lane & 3;
    float* vT = (float*)resid;   // EPI 3 only
#pragma unroll
    for (int mi = 0; mi < 2; mi++) {
#pragma unroll
        for (int nj = 0; nj < 8; nj++) {
            int r0 = m0 + wm * 32 + mi * 16 + g;
            int c0 = n0 + wn * 64 + nj * 8 + 2 * t;
            float2 bv = *(const float2*)(bias + c0);
#pragma unroll
            for (int half = 0; half < 2; half++) {
                int r = r0 + half * 8;
                float vx = acc[mi][nj][half * 2 + 0] + bv.x;
                float vy = acc[mi][nj][half * 2 + 1] + bv.y;
                if (EPI == 1) {
                    float2 rv = *(const float2*)(resid + (size_t)r * N + c0);
                    vx += rv.x; vy += rv.y;
                }
                if (EPI == 2) {
                    vx = 0.5f * vx * (1.f + erff(vx * 0.70710678118654752f));
                    vy = 0.5f * vy * (1.f + erff(vy * 0.70710678118654752f));
                    vx = rnd_tf32(vx); vy = rnd_tf32(vy);
                }
                if (EPI == 3) {
                    vx = rnd_tf32(vx); vy = rnd_tf32(vy);
                    if (c0 >= 2 * D_MODEL) {
                        vT[(size_t)(c0 - 2 * D_MODEL) * S_LEN + r] = vx;
                        vT[(size_t)(c0 + 1 - 2 * D_MODEL) * S_LEN + r] = vy;
                        continue;
                    }
                }
                *(float2*)(C + (size_t)r * N + c0) = make_float2(vx, vy);
            }
        }
    }
}

// ---------------- layernorm (tf32-rounded output) ----------------
__global__ __launch_bounds__(256)
void ln_kernel(const float* __restrict__ in, const float* __restrict__ gam,
               const float* __restrict__ bet, float* __restrict__ out)
{
    int row = blockIdx.x;
    int tid = threadIdx.x;
    const float* r = in + (size_t)row * D_MODEL;
    float v[8];
    float s = 0.f, s2 = 0.f;
#pragma unroll
    for (int i = 0; i < 8; i++) {
        v[i] = r[tid + i * 256];
        s += v[i]; s2 += v[i] * v[i];
    }
#pragma unroll
    for (int o = 16; o; o >>= 1) {
        s  += __shfl_xor_sync(0xffffffffu, s,  o);
        s2 += __shfl_xor_sync(0xffffffffu, s2, o);
    }
    __shared__ float sh0[8], sh1[8];
    if ((tid & 31) == 0) { sh0[tid >> 5] = s; sh1[tid >> 5] = s2; }
    __syncthreads();
    s = 0.f; s2 = 0.f;
#pragma unroll
    for (int i = 0; i < 8; i++) { s += sh0[i]; s2 += sh1[i]; }
    float mean = s * (1.f / D_MODEL);
    float var = s2 * (1.f / D_MODEL) - mean * mean;
    float rstd = rsqrtf(var + 1e-5f);
    float* w = out + (size_t)row * D_MODEL;
#pragma unroll
    for (int i = 0; i < 8; i++) {
        int c = tid + i * 256;
        w[c] = rnd_tf32((v[i] - mean) * rstd * gam[c] + bet[c]);
    }
}

// ================= tf32 MMA flash attention =================
// Block: 1 head x 128 queries. 8 warps, 16 q-rows each. K-tiles of 64 keys,
// cp.async double-buffered K (natural [key][dim]) and Vt ([dim][key]).
// SMEM (floats, stride 68): QP[128][68] (Q then reused for P), K[2][64][68], V[2][64][68].
#define AT_S 68
#define AT_QP 0
#define AT_K  (128 * AT_S)
#define AT_V  (AT_K + 2 * 64 * AT_S)
#define ATT_SMEM ((AT_V + 2 * 64 * AT_S) * 4)   // 104,448 B

__global__ __launch_bounds__(256)
void attn_mma(const float* __restrict__ qkv, const float* __restrict__ vT,
              const float* __restrict__ alibi, float* __restrict__ ctx)
{
    extern __shared__ float sm[];
    uint32_t sbase = smem_u32(sm);

    int tid = threadIdx.x;
    int lane = tid & 31, w = tid >> 5;
    int g = lane >> 2, t = lane & 3;
    int h = blockIdx.y;
    int q0 = (gridDim.x - 1 - blockIdx.x) * 128;   // longest first

    const float* ab = alibi + (size_t)h * S_LEN;
    const float inv = 0.125f;

    int midx = lane >> 3, mrow = lane & 7;
    int a_row_off = (midx & 1) * 8 + mrow;
    int a_col_off = (midx >> 1) * 4;
    int b_row_off = (midx >> 1) * 8 + mrow;
    int b_col_off = (midx & 1) * 4;

    // ---- loaders ----
    auto load_q = [&]() {
#pragma unroll
        for (int q = 0; q < 8; q++) {
            int idx = tid + q * 256;
            int row = idx >> 4, c4 = (idx & 15) * 4;
            cpa16(sbase + (uint32_t)(AT_QP + row * AT_S + c4) * 4,
                  qkv + (size_t)(q0 + row) * QKV_N + h * HDIM + c4);
        }
    };
    auto load_kv = [&](int st, int k0) {
        uint32_t kb = sbase + (uint32_t)(AT_K + st * 64 * AT_S) * 4;
        uint32_t vb = sbase + (uint32_t)(AT_V + st * 64 * AT_S) * 4;
#pragma unroll
        for (int q = 0; q < 4; q++) {
            int idx = tid + q * 256;
            int row = idx >> 4, c4 = (idx & 15) * 4;
            cpa16(kb + (uint32_t)(row * AT_S + c4) * 4,
                  qkv + (size_t)(k0 + row) * QKV_N + D_MODEL + h * HDIM + c4);
            cpa16(vb + (uint32_t)(row * AT_S + c4) * 4,
                  vT + (size_t)(h * HDIM + row) * S_LEN + k0 + c4);
        }
    };

    load_q();
    load_kv(0, 0);
    CP_COMMIT();
    CP_WAIT(0);
    __syncthreads();

    // Q fragments (stay in registers)
    uint32_t qf[8][4];
#pragma unroll
    for (int ks = 0; ks < 8; ks++) {
        int r = w * 16 + a_row_off;
        ldsm4(qf[ks], sbase + (uint32_t)(AT_QP + r * AT_S + ks * 8 + a_col_off) * 4);
    }
    __syncthreads();   // everyone done reading Q before P overwrites QP

    float oacc[8][4];
#pragma unroll
    for (int j = 0; j < 8; j++)
#pragma unroll
        for (int c = 0; c < 4; c++) oacc[j][c] = 0.f;
    float m0r = -1e30f, m1r = -1e30f, l0r = 0.f, l1r = 0.f;

    int qrow0 = q0 + w * 16 + g;       // row for c0,c1
    int qrow1 = qrow0 + 8;             // row for c2,c3

    const int T = (q0 + 128) / 64;

    for (int i = 0; i < T; i++) {
        int st = i & 1;
        int k0 = i * 64;
        if (i > 0) __syncthreads();        // all warps done with stage st^1
        if (i + 1 < T) {
            load_kv(st ^ 1, (i + 1) * 64);
            CP_COMMIT();
            CP_WAIT(1);
        } else {
            CP_WAIT(0);
        }
        __syncthreads();                   // stage st visible to all

        uint32_t kbse = sbase + (uint32_t)(AT_K + st * 64 * AT_S) * 4;
        uint32_t vbse = sbase + (uint32_t)(AT_V + st * 64 * AT_S) * 4;

        // ---- S = Q @ K^T ----
        float sacc[8][4];
#pragma unroll
        for (int j = 0; j < 8; j++)
#pragma unroll
            for (int c = 0; c < 4; c++) sacc[j][c] = 0.f;
#pragma unroll
        for (int ks = 0; ks < 8; ks++) {
            uint32_t bf[8][2];
#pragma unroll
            for (int jj = 0; jj < 4; jj++) {
                uint32_t t4[4];
                int r = jj * 16 + b_row_off;
                ldsm4(t4, kbse + (uint32_t)(r * AT_S + ks * 8 + b_col_off) * 4);
                bf[jj * 2 + 0][0] = t4[0]; bf[jj * 2 + 0][1] = t4[1];
                bf[jj * 2 + 1][0] = t4[2]; bf[jj * 2 + 1][1] = t4[3];
            }
#pragma unroll
            for (int nj = 0; nj < 8; nj++)
                mma_tf32(sacc[nj], qf[ks], bf[nj]);
        }

        // ---- softmax (online) ----
        float mx0 = -1e30f, mx1 = -1e30f;
#pragma unroll
        for (int nj = 0; nj < 8; nj++) {
            int kg = k0 + nj * 8 + 2 * t;
            float2 a2 = *(const float2*)(ab + kg);
            float v0 = (kg     <= qrow0) ? (sacc[nj][0] + a2.x) * inv : -1e30f;
            float v1 = (kg + 1 <= qrow0) ? (sacc[nj][1] + a2.y) * inv : -1e30f;
            float v2 = (kg     <= qrow1) ? (sacc[nj][2] + a2.x) * inv : -1e30f;
            float v3 = (kg + 1 <= qrow1) ? (sacc[nj][3] + a2.y) * inv : -1e30f;
            sacc[nj][0] = v0; sacc[nj][1] = v1; sacc[nj][2] = v2; sacc[nj][3] = v3;
            mx0 = fmaxf(mx0, fmaxf(v0, v1));
            mx1 = fmaxf(mx1, fmaxf(v2, v3));
        }
        mx0 = fmaxf(mx0, __shfl_xor_sync(0xffffffffu, mx0, 1));
        mx0 = fmaxf(mx0, __shfl_xor_sync(0xffffffffu, mx0, 2));
        mx1 = fmaxf(mx1, __shfl_xor_sync(0xffffffffu, mx1, 1));
        mx1 = fmaxf(mx1, __shfl_xor_sync(0xffffffffu, mx1, 2));

        float mn0 = fmaxf(m0r, mx0), mn1 = fmaxf(m1r, mx1);
        float sc0 = __expf(m0r - mn0), sc1 = __expf(m1r - mn1);
        m0r = mn0; m1r = mn1;
        l0r *= sc0; l1r *= sc1;
#pragma unroll
        for (int nj = 0; nj < 8; nj++) {
            oacc[nj][0] *= sc0; oacc[nj][1] *= sc0;
            oacc[nj][2] *= sc1; oacc[nj][3] *= sc1;
        }

        uint32_t pbase = sbase + (uint32_t)(AT_QP + (w * 16) * AT_S) * 4;
#pragma unroll
        for (int nj = 0; nj < 8; nj++) {
            float p0 = rnd_tf32(__expf(sacc[nj][0] - mn0));
            float p1 = rnd_tf32(__expf(sacc[nj][1] - mn0));
            float p2 = rnd_tf32(__expf(sacc[nj][2] - mn1));
            float p3 = rnd_tf32(__expf(sacc[nj][3] - mn1));
            l0r += p0 + p1; l1r += p2 + p3;
            int col = nj * 8 + 2 * t;
            asm volatile("st.shared.v2.b32 [%0], {%1,%2};"
                         :: "r"(pbase + (uint32_t)(g * AT_S + col) * 4),
                            "r"(__float_as_uint(p0)), "r"(__float_as_uint(p1)) : "memory");
            asm volatile("st.shared.v2.b32 [%0], {%1,%2};"
                         :: "r"(pbase + (uint32_t)((g + 8) * AT_S + col) * 4),
                            "r"(__float_as_uint(p2)), "r"(__float_as_uint(p3)) : "memory");
        }
        __syncwarp();

        // ---- O += P @ V ----
#pragma unroll
        for (int ks = 0; ks < 8; ks++) {
            uint32_t af[4];
            int r = w * 16 + a_row_off;
            ldsm4(af, sbase + (uint32_t)(AT_QP + r * AT_S + ks * 8 + a_col_off) * 4);
            uint32_t bf[8][2];
#pragma unroll
            for (int jj = 0; jj < 4; jj++) {
                uint32_t t4[4];
                int rr = jj * 16 + b_row_off;
                ldsm4(t4, vbse + (uint32_t)(rr * AT_S + ks * 8 + b_col_off) * 4);
                bf[jj * 2 + 0][0] = t4[0]; bf[jj * 2 + 0][1] = t4[1];
                bf[jj * 2 + 1][0] = t4[2]; bf[jj * 2 + 1][1] = t4[3];
            }
#pragma unroll
            for (int nj = 0; nj < 8; nj++)
                mma_tf32(oacc[nj], af, bf[nj]);
        }
        __syncwarp();   // P reads done before next tile overwrites
    }

    // ---- finalize: reduce l over quad, write ctx ----
    l0r += __shfl_xor_sync(0xffffffffu, l0r, 1);
    l0r += __shfl_xor_sync(0xffffffffu, l0r, 2);
    l1r += __shfl_xor_sync(0xffffffffu, l1r, 1);
    l1r += __shfl_xor_sync(0xffffffffu, l1r, 2);
    float r0 = 1.f / l0r, r1 = 1.f / l1r;

#pragma unroll
    for (int nj = 0; nj < 8; nj++) {
        int c = h * HDIM + nj * 8 + 2 * t;
        float2 o0 = make_float2(rnd_tf32(oacc[nj][0] * r0), rnd_tf32(oacc[nj][1] * r0));
        float2 o1 = make_float2(rnd_tf32(oacc[nj][2] * r1), rnd_tf32(oacc[nj][3] * r1));
        *(float2*)(ctx + (size_t)qrow0 * D_MODEL + c) = o0;
        *(float2*)(ctx + (size_t)qrow1 * D_MODEL + c) = o1;
    }
}

// ---------------- launch ----------------
extern "C" void kernel_launch(void* const* d_in, const int* in_sizes, int n_in,
                              void* d_out, int out_size)
{
    const float* x     = (const float*)d_in[0];
    const float* alibi = (const float*)d_in[1];
    const float* ln1g  = (const float*)d_in[3];
    const float* ln1b  = (const float*)d_in[4];
    const float* ln2g  = (const float*)d_in[5];
    const float* ln2b  = (const float*)d_in[6];
    const float* wqkv  = (const float*)d_in[7];
    const float* bqkv  = (const float*)d_in[8];
    const float* wo    = (const float*)d_in[9];
    const float* bo    = (const float*)d_in[10];
    const float* w1    = (const float*)d_in[11];
    const float* b1    = (const float*)d_in[12];
    const float* w2    = (const float*)d_in[13];
    const float* b2    = (const float*)d_in[14];
    float* out = (float*)d_out;

    float *h, *qkv, *vT, *ctx, *res, *h2, *mlp;
    float *wqkvT, *woT, *w1T, *w2T;
    cudaGetSymbolAddress((void**)&h,    g_h);
    cudaGetSymbolAddress((void**)&qkv,  g_qkv);
    cudaGetSymbolAddress((void**)&vT,   g_vT);
    cudaGetSymbolAddress((void**)&ctx,  g_ctx);
    cudaGetSymbolAddress((void**)&res,  g_res);
    cudaGetSymbolAddress((void**)&h2,   g_h2);
    cudaGetSymbolAddress((void**)&mlp,  g_mlp);
    cudaGetSymbolAddress((void**)&wqkvT, g_wqkvT);
    cudaGetSymbolAddress((void**)&woT,   g_woT);
    cudaGetSymbolAddress((void**)&w1T,   g_w1T);
    cudaGetSymbolAddress((void**)&w2T,   g_w2T);

    cudaFuncSetAttribute(mma_gemm<1>, cudaFuncAttributeMaxDynamicSharedMemorySize, GEMM_SMEM);
    cudaFuncSetAttribute(mma_gemm<2>, cudaFuncAttributeMaxDynamicSharedMemorySize, GEMM_SMEM);
    cudaFuncSetAttribute(mma_gemm<3>, cudaFuncAttributeMaxDynamicSharedMemorySize, GEMM_SMEM);
    cudaFuncSetAttribute(attn_mma, cudaFuncAttributeMaxDynamicSharedMemorySize, ATT_SMEM);

    // 0. weight transpose + tf32 round
    transpose_tf32<<<dim3(QKV_N / 32, D_MODEL / 32), 256>>>(wqkv, wqkvT, D_MODEL, QKV_N);
    transpose_tf32<<<dim3(D_MODEL / 32, D_MODEL / 32), 256>>>(wo, woT, D_MODEL, D_MODEL);
    transpose_tf32<<<dim3(FF_DIM / 32, D_MODEL / 32), 256>>>(w1, w1T, D_MODEL, FF_DIM);
    transpose_tf32<<<dim3(D_MODEL / 32, FF_DIM / 32), 256>>>(w2, w2T, FF_DIM, D_MODEL);

    // 1. h = tf32(LN1(x))
    ln_kernel<<<S_LEN, 256>>>(x, ln1g, ln1b, h);
    // 2. qkv = h @ wqkv + bqkv  (V part also written transposed to vT)
    mma_gemm<3><<<dim3(QKV_N / 128, S_LEN / 128), 256, GEMM_SMEM>>>(h, wqkvT, bqkv, vT, qkv,
                                                                    S_LEN, QKV_N, D_MODEL);
    // 3. ctx = tf32(flash attention, ALiBi + causal)
    attn_mma<<<dim3(S_LEN / 128, NHEAD), 256, ATT_SMEM>>>(qkv, vT, alibi, ctx);
    // 4. res = x + ctx @ wo + bo   (fp32)
    mma_gemm<1><<<dim3(D_MODEL / 128, S_LEN / 128), 256, GEMM_SMEM>>>(ctx, woT, bo, x, res,
                                                                      S_LEN, D_MODEL, D_MODEL);
    // 5. h2 = tf32(LN2(res))
    ln_kernel<<<S_LEN, 256>>>(res, ln2g, ln2b, h2);
    // 6. mlp = tf32(gelu(h2 @ w1 + b1))
    mma_gemm<2><<<dim3(FF_DIM / 128, S_LEN / 128), 256, GEMM_SMEM>>>(h2, w1T, b1, nullptr, mlp,
                                                                     S_LEN, FF_DIM, D_MODEL);
    // 7. out = res + mlp @ w2 + b2
    mma_gemm<1><<<dim3(D_MODEL / 128, S_LEN / 128), 256, GEMM_SMEM>>>(mlp, w2T, b2, res, out,
                                                                      S_LEN, D_MODEL, FF_DIM);
}

// round 11
// speedup vs baseline: 1.0076x; 1.0076x over previous
#include <cuda_runtime.h>
#include <cstdint>
#include <math.h>

#define S_LEN 2048
#define D_MODEL 2048
#define NHEAD 32
#define HDIM 64
#define FF_DIM 8192
#define QKV_N (3 * D_MODEL)

// ---------------- scratch (static device globals; no allocation) ----------------
__device__ float g_h  [S_LEN * D_MODEL];
__device__ float g_qkv[S_LEN * QKV_N];
__device__ float g_vT [D_MODEL * S_LEN];   // V transposed: [dim_global][seq]
__device__ float g_ctx[S_LEN * D_MODEL];
__device__ float g_res[S_LEN * D_MODEL];
__device__ float g_h2 [S_LEN * D_MODEL];
__device__ float g_mlp[S_LEN * FF_DIM];
// transposed tf32 weights (K-major)
__device__ float g_wqkvT[QKV_N * D_MODEL];
__device__ float g_woT  [D_MODEL * D_MODEL];
__device__ float g_w1T  [FF_DIM * D_MODEL];
__device__ float g_w2T  [D_MODEL * FF_DIM];

// ================= helpers =================
__device__ __forceinline__ uint32_t smem_u32(const void* p) {
    uint32_t a;
    asm("{ .reg .u64 t; cvta.to.shared.u64 t, %1; cvt.u32.u64 %0, t; }" : "=r"(a) : "l"(p));
    return a;
}
__device__ __forceinline__ uint32_t f2tf32(float f) {
    uint32_t u;
    asm("cvt.rna.tf32.f32 %0, %1;" : "=r"(u) : "f"(f));
    return u;
}
__device__ __forceinline__ float rnd_tf32(float f) { return __uint_as_float(f2tf32(f)); }

__device__ __forceinline__ void mma_tf32(float* d, const uint32_t* a, const uint32_t* b) {
    asm volatile(
        "mma.sync.aligned.m16n8k8.row.col.f32.tf32.tf32.f32 "
        "{%0,%1,%2,%3}, {%4,%5,%6,%7}, {%8,%9}, {%0,%1,%2,%3};"
        : "+f"(d[0]), "+f"(d[1]), "+f"(d[2]), "+f"(d[3])
        : "r"(a[0]), "r"(a[1]), "r"(a[2]), "r"(a[3]), "r"(b[0]), "r"(b[1]));
}
__device__ __forceinline__ void ldsm4(uint32_t* r, uint32_t addr) {
    asm volatile("ldmatrix.sync.aligned.m8n8.x4.shared.b16 {%0,%1,%2,%3}, [%4];"
                 : "=r"(r[0]), "=r"(r[1]), "=r"(r[2]), "=r"(r[3]) : "r"(addr));
}
__device__ __forceinline__ void cpa16(uint32_t dst, const float* src) {
    asm volatile("cp.async.cg.shared.global [%0], [%1], 16;" :: "r"(dst), "l"(src));
}
#define CP_COMMIT() asm volatile("cp.async.commit_group;" ::: "memory")
#define CP_WAIT(n)  asm volatile("cp.async.wait_group %0;" :: "n"(n) : "memory")

// ================= weight transpose + tf32 convert =================
__global__ __launch_bounds__(256)
void transpose_tf32(const float* __restrict__ W, float* __restrict__ WT, int K, int N)
{
    __shared__ float t[32][33];
    int n0 = blockIdx.x * 32, k0 = blockIdx.y * 32;
    int tx = threadIdx.x & 31, ty = threadIdx.x >> 5;
#pragma unroll
    for (int r = 0; r < 32; r += 8)
        t[ty + r][tx] = W[(size_t)(k0 + ty + r) * N + n0 + tx];
    __syncthreads();
#pragma unroll
    for (int r = 0; r < 32; r += 8)
        WT[(size_t)(n0 + ty + r) * K + k0 + tx] = rnd_tf32(t[tx][ty + r]);
}

// ================= tf32 tensor-core GEMM (pure cp.async + ldmatrix) ========
// C[M,N] = A[M,K] @ BT[N,K]^T.  128x128 block tile, K-chunk 32, double-buffered.
// 8 warps = 4(m) x 2(n); warp tile 32x64; mma m16n8k8.
// EPI 0: +bias   EPI 1: +bias+resid   EPI 2: tf32(gelu(+bias))
// EPI 3: QKV — tf32-rounded; V columns (c>=4096) written transposed to vT(resid ptr)
#define TS_STRIDE 36
#define A_TILE_F (128 * TS_STRIDE)
#define STAGE_F  (2 * A_TILE_F)
#define GEMM_SMEM (2 * STAGE_F * 4)     // 73,728 B

template<int EPI>
__global__ __launch_bounds__(256, 2)
void mma_gemm(const float* __restrict__ A, const float* __restrict__ BT,
              const float* __restrict__ bias, const float* __restrict__ resid,
              float* __restrict__ C, int M, int N, int K)
{
    extern __shared__ float sm[];
    uint32_t sbase = smem_u32(sm);

    int tid = threadIdx.x;
    int lane = tid & 31, wid = tid >> 5;
    int wm = wid & 3, wn = wid >> 2;
    int m0 = blockIdx.y * 128, n0 = blockIdx.x * 128;

    auto load_tile = [&](int st, int k0) {
        uint32_t base = sbase + (uint32_t)st * STAGE_F * 4;
        int r = tid >> 3, kq = tid & 7;
#pragma unroll
        for (int q = 0; q < 4; q++) {
            int row = r + q * 32;
            cpa16(base + (uint32_t)(row * TS_STRIDE + kq * 4) * 4,
                  A + (size_t)(m0 + row) * K + k0 + kq * 4);
        }
#pragma unroll
        for (int q = 0; q < 4; q++) {
            int row = r + q * 32;
            cpa16(base + (uint32_t)(A_TILE_F + row * TS_STRIDE + kq * 4) * 4,
                  BT + (size_t)(n0 + row) * K + k0 + kq * 4);
        }
        CP_COMMIT();
    };

    float acc[2][8][4];
#pragma unroll
    for (int i = 0; i < 2; i++)
#pragma unroll
        for (int j = 0; j < 8; j++)
#pragma unroll
            for (int c = 0; c < 4; c++) acc[i][j][c] = 0.f;

    int midx = lane >> 3, mrow = lane & 7;
    int a_row_off = (midx & 1) * 8 + mrow;
    int a_col_off = (midx >> 1) * 4;
    int b_row_base = wn * 64 + (midx >> 1) * 8 + mrow;
    int b_col_off = (midx & 1) * 4;

    const int T = K / 32;

    load_tile(0, 0);

    for (int i = 0; i < T; i++) {
        int st = i & 1;
        if (i + 1 < T) {
            load_tile(st ^ 1, (i + 1) * 32);
            CP_WAIT(1);
        } else {
            CP_WAIT(0);
        }
        __syncthreads();

        uint32_t abase = sbase + (uint32_t)st * STAGE_F * 4;
        uint32_t bbase = abase + A_TILE_F * 4;
#pragma unroll
        for (int ks = 0; ks < 4; ks++) {
            int kb = ks * 8;
            uint32_t af[2][4];
#pragma unroll
            for (int mi = 0; mi < 2; mi++) {
                int r = wm * 32 + mi * 16 + a_row_off;
                ldsm4(af[mi], abase + (uint32_t)(r * TS_STRIDE + kb + a_col_off) * 4);
            }
            uint32_t bf[8][2];
#pragma unroll
            for (int jj = 0; jj < 4; jj++) {
                uint32_t t4[4];
                int r = b_row_base + jj * 16;
                ldsm4(t4, bbase + (uint32_t)(r * TS_STRIDE + kb + b_col_off) * 4);
                bf[jj * 2 + 0][0] = t4[0]; bf[jj * 2 + 0][1] = t4[1];
                bf[jj * 2 + 1][0] = t4[2]; bf[jj * 2 + 1][1] = t4[3];
            }
#pragma unroll
            for (int mi = 0; mi < 2; mi++)
#pragma unroll
                for (int nj = 0; nj < 8; nj++)
                    mma_tf32(acc[mi][nj], af[mi], bf[nj]);
        }
        __syncthreads();
    }

    // ---- epilogue ----
    int g = lane >> 2, t = lane & 3;
    float* vT = (float*)resid;   // EPI 3 only
#pragma unroll
    for (int mi = 0; mi < 2; mi++) {
#pragma unroll
        for (int nj = 0; nj < 8; nj++) {
            int r0 = m0 + wm * 32 + mi * 16 + g;
            int c0 = n0 + wn * 64 + nj * 8 + 2 * t;
            float2 bv = *(const float2*)(bias + c0);
#pragma unroll
            for (int half = 0; half < 2; half++) {
                int r = r0 + half * 8;
                float vx = acc[mi][nj][half * 2 + 0] + bv.x;
                float vy = acc[mi][nj][half * 2 + 1] + bv.y;
                if (EPI == 1) {
                    float2 rv = *(const float2*)(resid + (size_t)r * N + c0);
                    vx += rv.x; vy += rv.y;
                }
                if (EPI == 2) {
                    vx = 0.5f * vx * (1.f + erff(vx * 0.70710678118654752f));
                    vy = 0.5f * vy * (1.f + erff(vy * 0.70710678118654752f));
                    vx = rnd_tf32(vx); vy = rnd_tf32(vy);
                }
                if (EPI == 3) {
                    vx = rnd_tf32(vx); vy = rnd_tf32(vy);
                    if (c0 >= 2 * D_MODEL) {
                        vT[(size_t)(c0 - 2 * D_MODEL) * S_LEN + r] = vx;
                        vT[(size_t)(c0 + 1 - 2 * D_MODEL) * S_LEN + r] = vy;
                        continue;
                    }
                }
                *(float2*)(C + (size_t)r * N + c0) = make_float2(vx, vy);
            }
        }
    }
}

// ---------------- layernorm (tf32-rounded output) ----------------
__global__ __launch_bounds__(256)
void ln_kernel(const float* __restrict__ in, const float* __restrict__ gam,
               const float* __restrict__ bet, float* __restrict__ out)
{
    int row = blockIdx.x;
    int tid = threadIdx.x;
    const float* r = in + (size_t)row * D_MODEL;
    float v[8];
    float s = 0.f, s2 = 0.f;
#pragma unroll
    for (int i = 0; i < 8; i++) {
        v[i] = r[tid + i * 256];
        s += v[i]; s2 += v[i] * v[i];
    }
#pragma unroll
    for (int o = 16; o; o >>= 1) {
        s  += __shfl_xor_sync(0xffffffffu, s,  o);
        s2 += __shfl_xor_sync(0xffffffffu, s2, o);
    }
    __shared__ float sh0[8], sh1[8];
    if ((tid & 31) == 0) { sh0[tid >> 5] = s; sh1[tid >> 5] = s2; }
    __syncthreads();
    s = 0.f; s2 = 0.f;
#pragma unroll
    for (int i = 0; i < 8; i++) { s += sh0[i]; s2 += sh1[i]; }
    float mean = s * (1.f / D_MODEL);
    float var = s2 * (1.f / D_MODEL) - mean * mean;
    float rstd = rsqrtf(var + 1e-5f);
    float* w = out + (size_t)row * D_MODEL;
#pragma unroll
    for (int i = 0; i < 8; i++) {
        int c = tid + i * 256;
        w[c] = rnd_tf32((v[i] - mean) * rstd * gam[c] + bet[c]);
    }
}

// ================= tf32 MMA flash attention =================
// Block: 1 head x 128 queries. 8 warps, 16 q-rows each. K-tiles of 64 keys,
// cp.async double-buffered K (natural [key][dim]) and Vt ([dim][key]).
// SMEM (floats, stride 68): QP[128][68] (Q then reused for P), K[2][64][68], V[2][64][68].
#define AT_S 68
#define AT_QP 0
#define AT_K  (128 * AT_S)
#define AT_V  (AT_K + 2 * 64 * AT_S)
#define ATT_SMEM ((AT_V + 2 * 64 * AT_S) * 4)   // 104,448 B

__global__ __launch_bounds__(256)
void attn_mma(const float* __restrict__ qkv, const float* __restrict__ vT,
              const float* __restrict__ alibi, float* __restrict__ ctx)
{
    extern __shared__ float sm[];
    uint32_t sbase = smem_u32(sm);

    int tid = threadIdx.x;
    int lane = tid & 31, w = tid >> 5;
    int g = lane >> 2, t = lane & 3;
    int h = blockIdx.y;
    int q0 = (gridDim.x - 1 - blockIdx.x) * 128;   // longest first

    const float* ab = alibi + (size_t)h * S_LEN;
    const float inv = 0.125f;

    int midx = lane >> 3, mrow = lane & 7;
    int a_row_off = (midx & 1) * 8 + mrow;
    int a_col_off = (midx >> 1) * 4;
    int b_row_off = (midx >> 1) * 8 + mrow;
    int b_col_off = (midx & 1) * 4;

    // ---- loaders ----
    auto load_q = [&]() {
#pragma unroll
        for (int q = 0; q < 8; q++) {
            int idx = tid + q * 256;
            int row = idx >> 4, c4 = (idx & 15) * 4;
            cpa16(sbase + (uint32_t)(AT_QP + row * AT_S + c4) * 4,
                  qkv + (size_t)(q0 + row) * QKV_N + h * HDIM + c4);
        }
    };
    auto load_kv = [&](int st, int k0) {
        uint32_t kb = sbase + (uint32_t)(AT_K + st * 64 * AT_S) * 4;
        uint32_t vb = sbase + (uint32_t)(AT_V + st * 64 * AT_S) * 4;
#pragma unroll
        for (int q = 0; q < 4; q++) {
            int idx = tid + q * 256;
            int row = idx >> 4, c4 = (idx & 15) * 4;
            cpa16(kb + (uint32_t)(row * AT_S + c4) * 4,
                  qkv + (size_t)(k0 + row) * QKV_N + D_MODEL + h * HDIM + c4);
            cpa16(vb + (uint32_t)(row * AT_S + c4) * 4,
                  vT + (size_t)(h * HDIM + row) * S_LEN + k0 + c4);
        }
    };

    load_q();
    load_kv(0, 0);
    CP_COMMIT();
    CP_WAIT(0);
    __syncthreads();

    // Q fragments (stay in registers)
    uint32_t qf[8][4];
#pragma unroll
    for (int ks = 0; ks < 8; ks++) {
        int r = w * 16 + a_row_off;
        ldsm4(qf[ks], sbase + (uint32_t)(AT_QP + r * AT_S + ks * 8 + a_col_off) * 4);
    }
    __syncthreads();   // everyone done reading Q before P overwrites QP

    float oacc[8][4];
#pragma unroll
    for (int j = 0; j < 8; j++)
#pragma unroll
        for (int c = 0; c < 4; c++) oacc[j][c] = 0.f;
    float m0r = -1e30f, m1r = -1e30f, l0r = 0.f, l1r = 0.f;

    int qrow0 = q0 + w * 16 + g;       // row for c0,c1
    int qrow1 = qrow0 + 8;             // row for c2,c3

    const int T = (q0 + 128) / 64;

    for (int i = 0; i < T; i++) {
        int st = i & 1;
        int k0 = i * 64;
        if (i > 0) __syncthreads();        // all warps done with stage st^1
        if (i + 1 < T) {
            load_kv(st ^ 1, (i + 1) * 64);
            CP_COMMIT();
            CP_WAIT(1);
        } else {
            CP_WAIT(0);
        }
        __syncthreads();                   // stage st visible to all

        uint32_t kbse = sbase + (uint32_t)(AT_K + st * 64 * AT_S) * 4;
        uint32_t vbse = sbase + (uint32_t)(AT_V + st * 64 * AT_S) * 4;

        // ---- S = Q @ K^T ----
        float sacc[8][4];
#pragma unroll
        for (int j = 0; j < 8; j++)
#pragma unroll
            for (int c = 0; c < 4; c++) sacc[j][c] = 0.f;
#pragma unroll
        for (int ks = 0; ks < 8; ks++) {
            uint32_t bf[8][2];
#pragma unroll
            for (int jj = 0; jj < 4; jj++) {
                uint32_t t4[4];
                int r = jj * 16 + b_row_off;
                ldsm4(t4, kbse + (uint32_t)(r * AT_S + ks * 8 + b_col_off) * 4);
                bf[jj * 2 + 0][0] = t4[0]; bf[jj * 2 + 0][1] = t4[1];
                bf[jj * 2 + 1][0] = t4[2]; bf[jj * 2 + 1][1] = t4[3];
            }
#pragma unroll
            for (int nj = 0; nj < 8; nj++)
                mma_tf32(sacc[nj], qf[ks], bf[nj]);
        }

        // ---- softmax (online) ----
        float mx0 = -1e30f, mx1 = -1e30f;
#pragma unroll
        for (int nj = 0; nj < 8; nj++) {
            int kg = k0 + nj * 8 + 2 * t;
            float2 a2 = *(const float2*)(ab + kg);
            float v0 = (kg     <= qrow0) ? (sacc[nj][0] + a2.x) * inv : -1e30f;
            float v1 = (kg + 1 <= qrow0) ? (sacc[nj][1] + a2.y) * inv : -1e30f;
            float v2 = (kg     <= qrow1) ? (sacc[nj][2] + a2.x) * inv : -1e30f;
            float v3 = (kg + 1 <= qrow1) ? (sacc[nj][3] + a2.y) * inv : -1e30f;
            sacc[nj][0] = v0; sacc[nj][1] = v1; sacc[nj][2] = v2; sacc[nj][3] = v3;
            mx0 = fmaxf(mx0, fmaxf(v0, v1));
            mx1 = fmaxf(mx1, fmaxf(v2, v3));
        }
        mx0 = fmaxf(mx0, __shfl_xor_sync(0xffffffffu, mx0, 1));
        mx0 = fmaxf(mx0, __shfl_xor_sync(0xffffffffu, mx0, 2));
        mx1 = fmaxf(mx1, __shfl_xor_sync(0xffffffffu, mx1, 1));
        mx1 = fmaxf(mx1, __shfl_xor_sync(0xffffffffu, mx1, 2));

        float mn0 = fmaxf(m0r, mx0), mn1 = fmaxf(m1r, mx1);
        float sc0 = __expf(m0r - mn0), sc1 = __expf(m1r - mn1);
        m0r = mn0; m1r = mn1;
        l0r *= sc0; l1r *= sc1;
#pragma unroll
        for (int nj = 0; nj < 8; nj++) {
            oacc[nj][0] *= sc0; oacc[nj][1] *= sc0;
            oacc[nj][2] *= sc1; oacc[nj][3] *= sc1;
        }

        uint32_t pbase = sbase + (uint32_t)(AT_QP + (w * 16) * AT_S) * 4;
#pragma unroll
        for (int nj = 0; nj < 8; nj++) {
            float p0 = rnd_tf32(__expf(sacc[nj][0] - mn0));
            float p1 = rnd_tf32(__expf(sacc[nj][1] - mn0));
            float p2 = rnd_tf32(__expf(sacc[nj][2] - mn1));
            float p3 = rnd_tf32(__expf(sacc[nj][3] - mn1));
            l0r += p0 + p1; l1r += p2 + p3;
            int col = nj * 8 + 2 * t;
            asm volatile("st.shared.v2.b32 [%0], {%1,%2};"
                         :: "r"(pbase + (uint32_t)(g * AT_S + col) * 4),
                            "r"(__float_as_uint(p0)), "r"(__float_as_uint(p1)) : "memory");
            asm volatile("st.shared.v2.b32 [%0], {%1,%2};"
                         :: "r"(pbase + (uint32_t)((g + 8) * AT_S + col) * 4),
                            "r"(__float_as_uint(p2)), "r"(__float_as_uint(p3)) : "memory");
        }
        __syncwarp();

        // ---- O += P @ V ----
#pragma unroll
        for (int ks = 0; ks < 8; ks++) {
            uint32_t af[4];
            int r = w * 16 + a_row_off;
            ldsm4(af, sbase + (uint32_t)(AT_QP + r * AT_S + ks * 8 + a_col_off) * 4);
            uint32_t bf[8][2];
#pragma unroll
            for (int jj = 0; jj < 4; jj++) {
                uint32_t t4[4];
                int rr = jj * 16 + b_row_off;
                ldsm4(t4, vbse + (uint32_t)(rr * AT_S + ks * 8 + b_col_off) * 4);
                bf[jj * 2 + 0][0] = t4[0]; bf[jj * 2 + 0][1] = t4[1];
                bf[jj * 2 + 1][0] = t4[2]; bf[jj * 2 + 1][1] = t4[3];
            }
#pragma unroll
            for (int nj = 0; nj < 8; nj++)
                mma_tf32(oacc[nj], af, bf[nj]);
        }
        __syncwarp();   // P reads done before next tile overwrites
    }

    // ---- finalize: reduce l over quad, write ctx ----
    l0r += __shfl_xor_sync(0xffffffffu, l0r, 1);
    l0r += __shfl_xor_sync(0xffffffffu, l0r, 2);
    l1r += __shfl_xor_sync(0xffffffffu, l1r, 1);
    l1r += __shfl_xor_sync(0xffffffffu, l1r, 2);
    float r0 = 1.f / l0r, r1 = 1.f / l1r;

#pragma unroll
    for (int nj = 0; nj < 8; nj++) {
        int c = h * HDIM + nj * 8 + 2 * t;
        float2 o0 = make_float2(rnd_tf32(oacc[nj][0] * r0), rnd_tf32(oacc[nj][1] * r0));
        float2 o1 = make_float2(rnd_tf32(oacc[nj][2] * r1), rnd_tf32(oacc[nj][3] * r1));
        *(float2*)(ctx + (size_t)qrow0 * D_MODEL + c) = o0;
        *(float2*)(ctx + (size_t)qrow1 * D_MODEL + c) = o1;
    }
}

// ---------------- launch ----------------
extern "C" void kernel_launch(void* const* d_in, const int* in_sizes, int n_in,
                              void* d_out, int out_size)
{
    const float* x     = (const float*)d_in[0];
    const float* alibi = (const float*)d_in[1];
    const float* ln1g  = (const float*)d_in[3];
    const float* ln1b  = (const float*)d_in[4];
    const float* ln2g  = (const float*)d_in[5];
    const float* ln2b  = (const float*)d_in[6];
    const float* wqkv  = (const float*)d_in[7];
    const float* bqkv  = (const float*)d_in[8];
    const float* wo    = (const float*)d_in[9];
    const float* bo    = (const float*)d_in[10];
    const float* w1    = (const float*)d_in[11];
    const float* b1    = (const float*)d_in[12];
    const float* w2    = (const float*)d_in[13];
    const float* b2    = (const float*)d_in[14];
    float* out = (float*)d_out;

    float *h, *qkv, *vT, *ctx, *res, *h2, *mlp;
    float *wqkvT, *woT, *w1T, *w2T;
    cudaGetSymbolAddress((void**)&h,    g_h);
    cudaGetSymbolAddress((void**)&qkv,  g_qkv);
    cudaGetSymbolAddress((void**)&vT,   g_vT);
    cudaGetSymbolAddress((void**)&ctx,  g_ctx);
    cudaGetSymbolAddress((void**)&res,  g_res);
    cudaGetSymbolAddress((void**)&h2,   g_h2);
    cudaGetSymbolAddress((void**)&mlp,  g_mlp);
    cudaGetSymbolAddress((void**)&wqkvT, g_wqkvT);
    cudaGetSymbolAddress((void**)&woT,   g_woT);
    cudaGetSymbolAddress((void**)&w1T,   g_w1T);
    cudaGetSymbolAddress((void**)&w2T,   g_w2T);

    cudaFuncSetAttribute(mma_gemm<1>, cudaFuncAttributeMaxDynamicSharedMemorySize, GEMM_SMEM);
    cudaFuncSetAttribute(mma_gemm<2>, cudaFuncAttributeMaxDynamicSharedMemorySize, GEMM_SMEM);
    cudaFuncSetAttribute(mma_gemm<3>, cudaFuncAttributeMaxDynamicSharedMemorySize, GEMM_SMEM);
    cudaFuncSetAttribute(attn_mma, cudaFuncAttributeMaxDynamicSharedMemorySize, ATT_SMEM);

    // 0. weight transpose + tf32 round
    transpose_tf32<<<dim3(QKV_N / 32, D_MODEL / 32), 256>>>(wqkv, wqkvT, D_MODEL, QKV_N);
    transpose_tf32<<<dim3(D_MODEL / 32, D_MODEL / 32), 256>>>(wo, woT, D_MODEL, D_MODEL);
    transpose_tf32<<<dim3(FF_DIM / 32, D_MODEL / 32), 256>>>(w1, w1T, D_MODEL, FF_DIM);
    transpose_tf32<<<dim3(D_MODEL / 32, FF_DIM / 32), 256>>>(w2, w2T, FF_DIM, D_MODEL);

    // 1. h = tf32(LN1(x))
    ln_kernel<<<S_LEN, 256>>>(x, ln1g, ln1b, h);
    // 2. qkv = h @ wqkv + bqkv  (V part also written transposed to vT)
    mma_gemm<3><<<dim3(QKV_N / 128, S_LEN / 128), 256, GEMM_SMEM>>>(h, wqkvT, bqkv, vT, qkv,
                                                                    S_LEN, QKV_N, D_MODEL);
    // 3. ctx = tf32(flash attention, ALiBi + causal)
    attn_mma<<<dim3(S_LEN / 128, NHEAD), 256, ATT_SMEM>>>(qkv, vT, alibi, ctx);
    // 4. res = x + ctx @ wo + bo   (fp32)
    mma_gemm<1><<<dim3(D_MODEL / 128, S_LEN / 128), 256, GEMM_SMEM>>>(ctx, woT, bo, x, res,
                                                                      S_LEN, D_MODEL, D_MODEL);
    // 5. h2 = tf32(LN2(res))
    ln_kernel<<<S_LEN, 256>>>(res, ln2g, ln2b, h2);
    // 6. mlp = tf32(gelu(h2 @ w1 + b1))
    mma_gemm<2><<<dim3(FF_DIM / 128, S_LEN / 128), 256, GEMM_SMEM>>>(h2, w1T, b1, nullptr, mlp,
                                                                     S_LEN, FF_DIM, D_MODEL);
    // 7. out = res + mlp @ w2 + b2
    mma_gemm<1><<<dim3(D_MODEL / 128, S_LEN / 128), 256, GEMM_SMEM>>>(mlp, w2T, b2, res, out,
                                                                      S_LEN, D_MODEL, FF_DIM);
}